// round 11
// baseline (speedup 1.0000x reference)
#include <cuda_runtime.h>
#include <cuda_bf16.h>

typedef unsigned int U32;

__device__ __forceinline__ U32 tf32r(float x) {
    U32 r;
    asm("cvt.rna.tf32.f32 %0, %1;" : "=r"(r) : "f"(x));
    return r;
}
__device__ __forceinline__ void mma_tf32(
    float& c0, float& c1, float& c2, float& c3,
    U32 a0, U32 a1, U32 a2, U32 a3, U32 b0, U32 b1)
{
    asm volatile(
        "mma.sync.aligned.m16n8k8.row.col.f32.tf32.tf32.f32 "
        "{%0,%1,%2,%3}, {%4,%5,%6,%7}, {%8,%9}, {%0,%1,%2,%3};"
        : "+f"(c0), "+f"(c1), "+f"(c2), "+f"(c3)
        : "r"(a0), "r"(a1), "r"(a2), "r"(a3), "r"(b0), "r"(b1));
}
__device__ __forceinline__ void mma_bf16(
    float& c0, float& c1, float& c2, float& c3,
    U32 a0, U32 a1, U32 a2, U32 a3, U32 b0, U32 b1)
{
    asm volatile(
        "mma.sync.aligned.m16n8k16.row.col.f32.bf16.bf16.f32 "
        "{%0,%1,%2,%3}, {%4,%5,%6,%7}, {%8,%9}, {%0,%1,%2,%3};"
        : "+f"(c0), "+f"(c1), "+f"(c2), "+f"(c3)
        : "r"(a0), "r"(a1), "r"(a2), "r"(a3), "r"(b0), "r"(b1));
}
__device__ __forceinline__ void cp16(U32 dst, const void* src) {
    asm volatile("cp.async.ca.shared.global [%0], [%1], 16;" :: "r"(dst), "l"(src));
}
__device__ __forceinline__ void cp_commit() { asm volatile("cp.async.commit_group;"); }
__device__ __forceinline__ void cp_wait1()  { asm volatile("cp.async.wait_group 1;"); }
__device__ __forceinline__ void cp_wait0()  { asm volatile("cp.async.wait_group 0;"); }

// bf16 hi/lo split. a = hi + lo + r, |r| <= 2^-18 |a|
__device__ __forceinline__ void bsplit(float v, unsigned short& hs, unsigned short& ls) {
    __nv_bfloat16 h = __float2bfloat16_rn(v);
    float hf = __bfloat162float(h);
    __nv_bfloat16 l = __float2bfloat16_rn(v - hf);
    hs = __bfloat16_as_ushort(h);
    ls = __bfloat16_as_ushort(l);
}
__device__ __forceinline__ U32 packA(float v) {
    unsigned short hs, ls; bsplit(v, hs, ls);
    return (U32)hs | ((U32)ls << 16);
}
// permute k within its 8-group so fragment LDS.64 gets (k, k+4) adjacent
__device__ __forceinline__ int permk(int k) {
    return (k & ~7) | ((k & 3) << 1) | ((k >> 2) & 1);
}

// Scratch (cudaMalloc forbidden; __device__ globals allowed)
__device__ U32   g_xp [1024 * 768];
__device__ U32   g_swh[256 * 768], g_swl[256 * 768];
__device__ U32   g_twh[256 * 768], g_twl[256 * 768];
__device__ U32   g_w2h[256 * 512], g_w2l[256 * 512];
__device__ U32   g_w3p[25 * 256];                 // fc3 tf32 bits, k-permuted
__device__ U32   g_s  [1024 * 256];               // stage1 out, packed-split, permuted
__device__ U32   g_t  [1024 * 256];
__device__ float g_s2 [1024 * 256];               // stage2 out, fp32, h-permuted
__device__ float g_t2 [1024 * 256];

#define NX  (1024 * 768)
#define NW  (256 * 768)
#define NW2 (256 * 512)
#define NW3 (25 * 256)

__global__ void prep(const float* __restrict__ X,
                     const float* __restrict__ sw, const float* __restrict__ tw,
                     const float* __restrict__ w2, const float* __restrict__ w3)
{
    int i = blockIdx.x * blockDim.x + threadIdx.x;
    if (i < NX) {
        int row = i / 768, k = i % 768;
        g_xp[row * 768 + permk(k)] = packA(X[i]);
    }
    if (i < NW) {
        int row = i / 768, k = i % 768;
        int o = row * 768 + permk(k);
        unsigned short hs, ls;
        bsplit(sw[i], hs, ls);
        g_swh[o] = (U32)hs | ((U32)hs << 16);
        g_swl[o] = (U32)ls;
        bsplit(tw[i], hs, ls);
        g_twh[o] = (U32)hs | ((U32)hs << 16);
        g_twl[o] = (U32)ls;
    }
    if (i < NW2) {
        int row = i / 512, k = i % 512;
        int o = row * 512 + permk(k);
        unsigned short hs, ls;
        bsplit(w2[i], hs, ls);
        g_w2h[o] = (U32)hs | ((U32)hs << 16);
        g_w2l[o] = (U32)ls;
    }
    if (i < NW3) {
        int row = i / 256, k = i % 256;
        g_w3p[row * 256 + permk(k)] = tf32r(w3[i]);
    }
}

// ---------------------------------------------------------------------------
// gemm_bf v3 (warp-autonomous): C[m][n] = act( sum_k A[m][k]*B[n][k] + bias ),
// fp32-accurate via packed bf16-split (D += A x Bhh + A x Bl0, m16n8k16).
// ZERO __syncthreads in the mainloop: each warp owns private double-buffered
// smem (its 16-row A half + 16-row Bh/Bl half, duplicated across warps) and
// runs its own cp.async pipeline with wait_group + __syncwarp only.
// CTA 32m x 32n, 128 threads (4 warps). 512 CTAs. smem 61.4 KB dynamic.
// packOut: 0 = plain fp32, 1 = packed-split U32 (permuted), 2 = fp32 permuted.
// ---------------------------------------------------------------------------
#define SKW 40
#define OF_BH (16 * SKW)            // 640
#define OF_BL (32 * SKW)            // 1280
#define WBUF  (48 * SKW)            // 1920 words per buffer
#define GEMM_SMEM (4 * 2 * WBUF * 4)   // 61440 bytes

__global__ __launch_bounds__(128) void gemm_bf(
    const U32* __restrict__ A0,  const U32* __restrict__ A1,
    const U32* __restrict__ Bh0, const U32* __restrict__ Bh1,
    const U32* __restrict__ Bl0, const U32* __restrict__ Bl1,
    const float* __restrict__ bias0, const float* __restrict__ bias1,
    void* C0, void* C1,
    int K, int ldb, int N, int relu, int packOut)
{
    extern __shared__ U32 smw[];

    const U32* A      = blockIdx.z ? A1 : A0;
    const U32* Bhp    = blockIdx.z ? Bh1 : Bh0;
    const U32* Blp    = blockIdx.z ? Bl1 : Bl0;
    const float* bias = blockIdx.z ? bias1 : bias0;
    void* C           = blockIdx.z ? C1 : C0;

    const int m0 = blockIdx.y * 32;
    const int n0 = blockIdx.x * 32;

    const int tid  = threadIdx.x;
    const int w    = tid >> 5;
    const int lane = tid & 31;
    const int g    = lane >> 2;
    const int tg   = lane & 3;
    const int r0   = (w & 1) * 16 + g;     // global m rows r0, r0+8 (within tile)
    const int nb   = (w >> 1) * 16;        // n half

    U32* mysm = smw + w * 2 * WBUF;        // this warp's two buffers
    const U32 smB = (U32)__cvta_generic_to_shared(mysm);

    // loader: lane -> row lane>>1 (0..15), words (lane&1)*16 .. +15 (4 cp16/array)
    const int arow = lane >> 1;
    const int ak   = (lane & 1) * 16;

    const U32* Aptr  = A   + (size_t)(m0 + (w & 1) * 16 + arow) * K   + ak;
    const U32* Bhptr = Bhp + (size_t)(n0 + nb + arow) * ldb + ak;
    const U32* Blptr = Blp + (size_t)(n0 + nb + arow) * ldb + ak;

    const int KC = K / 32;

    float acc[2][4];
#pragma unroll
    for (int nt = 0; nt < 2; nt++)
#pragma unroll
        for (int c = 0; c < 4; c++) acc[nt][c] = 0.f;

    {   // stage chunk 0 into buf 0
#pragma unroll
        for (int c = 0; c < 4; c++) {
            cp16(smB + (        arow * SKW + ak + c * 4) * 4, Aptr  + c * 4);
            cp16(smB + (OF_BH + arow * SKW + ak + c * 4) * 4, Bhptr + c * 4);
            cp16(smB + (OF_BL + arow * SKW + ak + c * 4) * 4, Blptr + c * 4);
        }
        cp_commit();
    }

    for (int kc = 0; kc < KC; kc++) {
        const int cur = kc & 1;
        if (kc + 1 < KC) {
            const int ko = (kc + 1) * 32;
            const U32 nb32 = smB + (cur ^ 1) * WBUF * 4;
#pragma unroll
            for (int c = 0; c < 4; c++) {
                cp16(nb32 + (        arow * SKW + ak + c * 4) * 4, Aptr  + ko + c * 4);
                cp16(nb32 + (OF_BH + arow * SKW + ak + c * 4) * 4, Bhptr + ko + c * 4);
                cp16(nb32 + (OF_BL + arow * SKW + ak + c * 4) * 4, Blptr + ko + c * 4);
            }
            cp_commit();
            cp_wait1();
        } else {
            cp_wait0();
        }
        __syncwarp();

        const U32* base = mysm + cur * WBUF;
#pragma unroll
        for (int ks = 0; ks < 4; ks++) {
            const int o = ks * 8 + 2 * tg;
            uint2 aA = *(const uint2*)&base[ g      * SKW + o];
            uint2 aB = *(const uint2*)&base[(g + 8) * SKW + o];
#pragma unroll
            for (int nt = 0; nt < 2; nt++) {
                uint2 bh = *(const uint2*)&base[OF_BH + (nt * 8 + g) * SKW + o];
                uint2 bl = *(const uint2*)&base[OF_BL + (nt * 8 + g) * SKW + o];
                mma_bf16(acc[nt][0], acc[nt][1], acc[nt][2], acc[nt][3],
                         aA.x, aB.x, aA.y, aB.y, bh.x, bh.y);
                mma_bf16(acc[nt][0], acc[nt][1], acc[nt][2], acc[nt][3],
                         aA.x, aB.x, aA.y, aB.y, bl.x, bl.y);
            }
        }
        __syncwarp();
    }

    // epilogue: c0:(r0,2tg) c1:(r0,2tg+1) c2:(r0+8,2tg) c3:(r0+8,2tg+1)
#pragma unroll
    for (int nt = 0; nt < 2; nt++) {
#pragma unroll
        for (int cc = 0; cc < 2; cc++) {
            const int r   = 2 * tg + cc;
            const int col = n0 + nb + nt * 8 + r;
            float bv = bias ? bias[col] : 0.f;
            float v0 = acc[nt][cc]     + bv;
            float v1 = acc[nt][cc + 2] + bv;
            if (relu) { v0 = fmaxf(v0, 0.f); v1 = fmaxf(v1, 0.f); }
            const int pcol = n0 + nb + nt * 8 + (((r & 3) << 1) | ((r >> 2) & 1));
            if (packOut == 1) {
                ((U32*)C)[(size_t)(m0 + r0)     * N + pcol] = packA(v0);
                ((U32*)C)[(size_t)(m0 + r0 + 8) * N + pcol] = packA(v1);
            } else if (packOut == 2) {
                ((float*)C)[(size_t)(m0 + r0)     * N + pcol] = v0;
                ((float*)C)[(size_t)(m0 + r0 + 8) * N + pcol] = v1;
            } else {
                ((float*)C)[(size_t)(m0 + r0)     * N + col] = v0;
                ((float*)C)[(size_t)(m0 + r0 + 8) * N + col] = v1;
            }
        }
    }
}

// ---------------------------------------------------------------------------
// pair_mma v4 (unchanged from R10 — measured 34.0 us, occ 32.8%):
// out[b,i,n,j] = sum_h relu(s2[b,i,h] + t2[b,j,h]) * fc3[n,h]
// tf32 m16n8k8; pair fragments built in registers, never materialized.
// smem 68.6 KB -> 3 CTAs/SM; staging pure cp.async from pre-permuted gmem.
// W stores only 25 real rows; nt=3 rows 25..31 alias the s region (finite
// floats) and feed only the discarded n>=25 output columns.
// ---------------------------------------------------------------------------
#define PROW 264
#define PROW2 132
#define SM_T2F 0
#define SM_WF  (32 * PROW)
#define SM_SF  (57 * PROW)
#define PAIR_SMEM (65 * PROW * 4)   // 68640 B

__global__ __launch_bounds__(256, 3) void pair_mma(
    const float* __restrict__ s2, const float* __restrict__ t2,
    const U32* __restrict__ w3p, float* __restrict__ out)
{
    extern __shared__ float sm[];
    const int jt = blockIdx.x;   // 0..7  (j tile of 32)
    const int ig = blockIdx.y;   // 0..31 (i group of 8)
    const int b  = blockIdx.z;   // 0..3

    const int tid  = threadIdx.x;
    const int w    = tid >> 5;
    const int lane = tid & 31;
    const int g    = lane >> 2;
    const int tg   = lane & 3;
    const int wj   = w & 1;
    const int wi   = w >> 1;

    const U32 smB = (U32)__cvta_generic_to_shared(sm);

    {   // t2: 32 rows x 256 floats
        const float* t2g = t2 + (size_t)(b * 256 + jt * 32) * 256;
#pragma unroll
        for (int r = 0; r < 8; r++) {
            int q   = tid + r * 256;
            int row = q >> 6;
            int c4  = (q & 63) * 4;
            cp16(smB + (SM_T2F + row * PROW + c4) * 4, t2g + row * 256 + c4);
        }
    }
    // fc3 tf32: 25 rows x 256
    for (int q = tid; q < 1600; q += 256) {
        int row = q >> 6;
        int c4  = (q & 63) * 4;
        cp16(smB + (SM_WF + row * PROW + c4) * 4, w3p + row * 256 + c4);
    }
    {   // s2: 8 rows x 256
        const float* s2g = s2 + (size_t)(b * 256 + ig * 8) * 256;
#pragma unroll
        for (int r = 0; r < 2; r++) {
            int q   = tid + r * 256;
            int row = q >> 6;
            int c4  = (q & 63) * 4;
            cp16(smB + (SM_SF + row * PROW + c4) * 4, s2g + row * 256 + c4);
        }
    }
    cp_commit();
    cp_wait0();
    __syncthreads();

    const float2* tA2 = (const float2*)sm + (size_t)(wj * 16 + g) * PROW2 + tg;
    const float2* tW2 = (const float2*)sm + (SM_WF / 2) + (size_t)g * PROW2 + tg;
    const float2* tS2 = (const float2*)sm + (SM_SF / 2) + (size_t)(wi * 2) * PROW2 + tg;

    float acc[2][4][4];   // [i][nt][c]
#pragma unroll
    for (int i = 0; i < 2; i++)
#pragma unroll
        for (int nt = 0; nt < 4; nt++)
#pragma unroll
            for (int c = 0; c < 4; c++) acc[i][nt][c] = 0.f;

#pragma unroll 4
    for (int ks = 0; ks < 32; ks++) {
        const int o = ks * 4;
        float2 u0 = tA2[o];
        float2 u1 = tA2[o + 8 * PROW2];
        float2 wv[4];
#pragma unroll
        for (int nt = 0; nt < 4; nt++) wv[nt] = tW2[o + nt * 8 * PROW2];
#pragma unroll
        for (int i = 0; i < 2; i++) {
            float2 sv = tS2[o + i * PROW2];
            U32 a0 = tf32r(fmaxf(u0.x + sv.x, 0.f));
            U32 a1 = tf32r(fmaxf(u1.x + sv.x, 0.f));
            U32 a2 = tf32r(fmaxf(u0.y + sv.y, 0.f));
            U32 a3 = tf32r(fmaxf(u1.y + sv.y, 0.f));
#pragma unroll
            for (int nt = 0; nt < 4; nt++) {
                mma_tf32(acc[i][nt][0], acc[i][nt][1], acc[i][nt][2], acc[i][nt][3],
                         a0, a1, a2, a3,
                         __float_as_uint(wv[nt].x), __float_as_uint(wv[nt].y));
            }
        }
    }

    const int jg = jt * 32 + wj * 16 + g;
#pragma unroll
    for (int i = 0; i < 2; i++) {
        const int ii = ig * 8 + wi * 2 + i;
        float* obase = out + ((size_t)(b * 256 + ii) * 25) * 256 + jg;
#pragma unroll
        for (int nt = 0; nt < 4; nt++) {
            int n0 = nt * 8 + tg * 2;
            if (n0 < 25) {
                obase[(size_t)n0 * 256]     = acc[i][nt][0];
                obase[(size_t)n0 * 256 + 8] = acc[i][nt][2];
            }
            if (n0 + 1 < 25) {
                obase[(size_t)(n0 + 1) * 256]     = acc[i][nt][1];
                obase[(size_t)(n0 + 1) * 256 + 8] = acc[i][nt][3];
            }
        }
    }
}

// ---------------------------------------------------------------------------
// Inputs (metadata order):
// 0 input_tensor [4,256,768]  1 s_fc_w [256,768]  2 s_fc_b [256]
// 3 t_fc_w [256,768]          4 t_fc_b [256]      5 fc2_w [256,512]
// 6 fc2_b [256]               7 fc3_w [25,256]
// Output: float32 [4,256,25,256]
// ---------------------------------------------------------------------------
extern "C" void kernel_launch(void* const* d_in, const int* in_sizes, int n_in,
                              void* d_out, int out_size)
{
    const float* X  = (const float*)d_in[0];
    const float* sw = (const float*)d_in[1];
    const float* sb = (const float*)d_in[2];
    const float* tw = (const float*)d_in[3];
    const float* tb = (const float*)d_in[4];
    const float* w2 = (const float*)d_in[5];
    const float* b2 = (const float*)d_in[6];
    const float* w3 = (const float*)d_in[7];
    float* out = (float*)d_out;

    U32 *xp, *swh, *swl, *twh, *twl, *w2h, *w2l, *w3p, *gs, *gt;
    float *gs2, *gt2;
    cudaGetSymbolAddress((void**)&xp,  g_xp);
    cudaGetSymbolAddress((void**)&swh, g_swh);
    cudaGetSymbolAddress((void**)&swl, g_swl);
    cudaGetSymbolAddress((void**)&twh, g_twh);
    cudaGetSymbolAddress((void**)&twl, g_twl);
    cudaGetSymbolAddress((void**)&w2h, g_w2h);
    cudaGetSymbolAddress((void**)&w2l, g_w2l);
    cudaGetSymbolAddress((void**)&w3p, g_w3p);
    cudaGetSymbolAddress((void**)&gs,  g_s);
    cudaGetSymbolAddress((void**)&gt,  g_t);
    cudaGetSymbolAddress((void**)&gs2, g_s2);
    cudaGetSymbolAddress((void**)&gt2, g_t2);

    cudaFuncSetAttribute(gemm_bf, cudaFuncAttributeMaxDynamicSharedMemorySize,
                         GEMM_SMEM);
    cudaFuncSetAttribute(pair_mma, cudaFuncAttributeMaxDynamicSharedMemorySize,
                         PAIR_SMEM);

    prep<<<(NX + 255) / 256, 256>>>(X, sw, tw, w2, w3);

    dim3 blk(128);
    dim3 g1(256 / 32, 1024 / 32, 2);   // 512 CTAs
    gemm_bf<<<g1, blk, GEMM_SMEM>>>(xp, xp, swh, twh, swl, twl, sb, tb,
                                    gs, gt, 768, 768, 256, 1, 1);
    // s2/t2 written fp32 with h-permutation (packOut=2) for pair staging
    gemm_bf<<<g1, blk, GEMM_SMEM>>>(gs, gt, w2h, w2h + 256, w2l, w2l + 256,
                                    nullptr, b2, gs2, gt2, 256, 512, 256, 0, 2);

    dim3 g3(8, 32, 4);                 // 1024 CTAs, 256 threads
    pair_mma<<<g3, dim3(256), PAIR_SMEM>>>(gs2, gt2, w3p, out);
}

// round 12
// speedup vs baseline: 1.1363x; 1.1363x over previous
#include <cuda_runtime.h>
#include <cuda_bf16.h>

typedef unsigned int U32;

__device__ __forceinline__ U32 tf32r(float x) {
    U32 r;
    asm("cvt.rna.tf32.f32 %0, %1;" : "=r"(r) : "f"(x));
    return r;
}
__device__ __forceinline__ void mma_tf32(
    float& c0, float& c1, float& c2, float& c3,
    U32 a0, U32 a1, U32 a2, U32 a3, U32 b0, U32 b1)
{
    asm volatile(
        "mma.sync.aligned.m16n8k8.row.col.f32.tf32.tf32.f32 "
        "{%0,%1,%2,%3}, {%4,%5,%6,%7}, {%8,%9}, {%0,%1,%2,%3};"
        : "+f"(c0), "+f"(c1), "+f"(c2), "+f"(c3)
        : "r"(a0), "r"(a1), "r"(a2), "r"(a3), "r"(b0), "r"(b1));
}
__device__ __forceinline__ void mma_bf16(
    float& c0, float& c1, float& c2, float& c3,
    U32 a0, U32 a1, U32 a2, U32 a3, U32 b0, U32 b1)
{
    asm volatile(
        "mma.sync.aligned.m16n8k16.row.col.f32.bf16.bf16.f32 "
        "{%0,%1,%2,%3}, {%4,%5,%6,%7}, {%8,%9}, {%0,%1,%2,%3};"
        : "+f"(c0), "+f"(c1), "+f"(c2), "+f"(c3)
        : "r"(a0), "r"(a1), "r"(a2), "r"(a3), "r"(b0), "r"(b1));
}
__device__ __forceinline__ void cp16(U32 dst, const void* src) {
    asm volatile("cp.async.ca.shared.global [%0], [%1], 16;" :: "r"(dst), "l"(src));
}
__device__ __forceinline__ void cp_commit() { asm volatile("cp.async.commit_group;"); }
__device__ __forceinline__ void cp_wait0()  { asm volatile("cp.async.wait_group 0;"); }

// bf16 hi/lo split. a = hi + lo + r, |r| <= 2^-18 |a|
__device__ __forceinline__ void bsplit(float v, unsigned short& hs, unsigned short& ls) {
    __nv_bfloat16 h = __float2bfloat16_rn(v);
    float hf = __bfloat162float(h);
    __nv_bfloat16 l = __float2bfloat16_rn(v - hf);
    hs = __bfloat16_as_ushort(h);
    ls = __bfloat16_as_ushort(l);
}
__device__ __forceinline__ U32 packA(float v) {
    unsigned short hs, ls; bsplit(v, hs, ls);
    return (U32)hs | ((U32)ls << 16);
}
// permute k within its 8-group so fragment LDS.64 gets (k, k+4) adjacent
__device__ __forceinline__ int permk(int k) {
    return (k & ~7) | ((k & 3) << 1) | ((k >> 2) & 1);
}

// Scratch (cudaMalloc forbidden; __device__ globals allowed)
__device__ U32   g_xp [1024 * 768];
__device__ U32   g_swh[256 * 768], g_swl[256 * 768];
__device__ U32   g_twh[256 * 768], g_twl[256 * 768];
__device__ U32   g_w2h[256 * 512], g_w2l[256 * 512];
__device__ U32   g_w3p[25 * 256];                 // fc3 tf32 bits, k-permuted
__device__ U32   g_s  [1024 * 256];               // stage1 out, packed-split, permuted
__device__ U32   g_t  [1024 * 256];
__device__ float g_s2 [1024 * 256];               // stage2 out, fp32, h-permuted
__device__ float g_t2 [1024 * 256];

#define NX  (1024 * 768)
#define NW  (256 * 768)
#define NW2 (256 * 512)
#define NW3 (25 * 256)

__global__ void prep(const float* __restrict__ X,
                     const float* __restrict__ sw, const float* __restrict__ tw,
                     const float* __restrict__ w2, const float* __restrict__ w3)
{
    int i = blockIdx.x * blockDim.x + threadIdx.x;
    if (i < NX) {
        int row = i / 768, k = i % 768;
        g_xp[row * 768 + permk(k)] = packA(X[i]);
    }
    if (i < NW) {
        int row = i / 768, k = i % 768;
        int o = row * 768 + permk(k);
        unsigned short hs, ls;
        bsplit(sw[i], hs, ls);
        g_swh[o] = (U32)hs | ((U32)hs << 16);
        g_swl[o] = (U32)ls;
        bsplit(tw[i], hs, ls);
        g_twh[o] = (U32)hs | ((U32)hs << 16);
        g_twl[o] = (U32)ls;
    }
    if (i < NW2) {
        int row = i / 512, k = i % 512;
        int o = row * 512 + permk(k);
        unsigned short hs, ls;
        bsplit(w2[i], hs, ls);
        g_w2h[o] = (U32)hs | ((U32)hs << 16);
        g_w2l[o] = (U32)ls;
    }
    if (i < NW3) {
        int row = i / 256, k = i % 256;
        g_w3p[row * 256 + permk(k)] = tf32r(w3[i]);
    }
}

// ---------------------------------------------------------------------------
// gemm_bf v4: block-shared tiles (R10 structure), K-chunk 64, ONE
// __syncthreads per chunk (wait -> sync -> prefetch nxt -> compute cur:
// prefetch targets the buffer everyone finished reading before the sync).
// Row stride 76 words -> conflict-free fragment LDS.64 (12g mod 32 is a
// permutation). CTA 32m x 32n, 128 threads. 512 CTAs. smem 58.4 KB dynamic.
// packOut: 0 = plain fp32, 1 = packed-split U32 (permuted), 2 = fp32 permuted.
// ---------------------------------------------------------------------------
#define SKW 76
#define ARR (32 * SKW)                    // words per array (2432)
#define GBUF (3 * ARR)                    // A + Bh + Bl per buffer
#define GEMM_SMEM (2 * GBUF * 4)          // 58368 bytes

__global__ __launch_bounds__(128) void gemm_bf(
    const U32* __restrict__ A0,  const U32* __restrict__ A1,
    const U32* __restrict__ Bh0, const U32* __restrict__ Bh1,
    const U32* __restrict__ Bl0, const U32* __restrict__ Bl1,
    const float* __restrict__ bias0, const float* __restrict__ bias1,
    void* C0, void* C1,
    int K, int ldb, int N, int relu, int packOut)
{
    extern __shared__ U32 smw[];

    const U32* A      = blockIdx.z ? A1 : A0;
    const U32* Bhp    = blockIdx.z ? Bh1 : Bh0;
    const U32* Blp    = blockIdx.z ? Bl1 : Bl0;
    const float* bias = blockIdx.z ? bias1 : bias0;
    void* C           = blockIdx.z ? C1 : C0;

    const int m0 = blockIdx.y * 32;
    const int n0 = blockIdx.x * 32;

    const int tid  = threadIdx.x;
    const int w    = tid >> 5;
    const int lane = tid & 31;
    const int g    = lane >> 2;
    const int tg   = lane & 3;
    const int r0   = (w & 1) * 16 + g;     // m rows r0, r0+8
    const int nb   = (w >> 1) * 16;        // n half

    const U32 smB = (U32)__cvta_generic_to_shared(smw);

    // loader: 128 threads, chunk = 32 rows x 64 words per array.
    // thread -> row tid>>2 (0..31), words (tid&3)*16 .. +15 (4 cp16/array)
    const int lrow = tid >> 2;
    const int lk   = (tid & 3) * 16;

    const U32* Aptr  = A   + (size_t)(m0 + lrow) * K   + lk;
    const U32* Bhptr = Bhp + (size_t)(n0 + lrow) * ldb + lk;
    const U32* Blptr = Blp + (size_t)(n0 + lrow) * ldb + lk;

    const int KC = K / 64;

    float acc[2][4];
#pragma unroll
    for (int nt = 0; nt < 2; nt++)
#pragma unroll
        for (int c = 0; c < 4; c++) acc[nt][c] = 0.f;

    {   // stage chunk 0 into buf 0
        const U32 d = smB + (lrow * SKW + lk) * 4;
#pragma unroll
        for (int c = 0; c < 4; c++) {
            cp16(d +              c * 16, Aptr  + c * 4);
            cp16(d + ARR  * 4   + c * 16, Bhptr + c * 4);
            cp16(d + ARR  * 8   + c * 16, Blptr + c * 4);
        }
        cp_commit();
    }

    for (int kc = 0; kc < KC; kc++) {
        const int cur = kc & 1;
        cp_wait0();
        __syncthreads();
        // prefetch next chunk into the other buffer (safe: everyone finished
        // reading it before the sync above)
        if (kc + 1 < KC) {
            const int ko = (kc + 1) * 64;
            const U32 d = smB + (cur ^ 1) * GBUF * 4 + (lrow * SKW + lk) * 4;
#pragma unroll
            for (int c = 0; c < 4; c++) {
                cp16(d +            c * 16, Aptr  + ko + c * 4);
                cp16(d + ARR * 4  + c * 16, Bhptr + ko + c * 4);
                cp16(d + ARR * 8  + c * 16, Blptr + ko + c * 4);
            }
            cp_commit();
        }

        const U32* base = smw + cur * GBUF;
#pragma unroll
        for (int ks = 0; ks < 8; ks++) {
            const int o = ks * 8 + 2 * tg;
            uint2 aA = *(const uint2*)&base[ r0      * SKW + o];
            uint2 aB = *(const uint2*)&base[(r0 + 8) * SKW + o];
#pragma unroll
            for (int nt = 0; nt < 2; nt++) {
                uint2 bh = *(const uint2*)&base[ARR     + (nb + nt * 8 + g) * SKW + o];
                uint2 bl = *(const uint2*)&base[ARR * 2 + (nb + nt * 8 + g) * SKW + o];
                mma_bf16(acc[nt][0], acc[nt][1], acc[nt][2], acc[nt][3],
                         aA.x, aB.x, aA.y, aB.y, bh.x, bh.y);
                mma_bf16(acc[nt][0], acc[nt][1], acc[nt][2], acc[nt][3],
                         aA.x, aB.x, aA.y, aB.y, bl.x, bl.y);
            }
        }
    }

    // epilogue: c0:(r0,2tg) c1:(r0,2tg+1) c2:(r0+8,2tg) c3:(r0+8,2tg+1)
#pragma unroll
    for (int nt = 0; nt < 2; nt++) {
#pragma unroll
        for (int cc = 0; cc < 2; cc++) {
            const int r   = 2 * tg + cc;
            const int col = n0 + nb + nt * 8 + r;
            float bv = bias ? bias[col] : 0.f;
            float v0 = acc[nt][cc]     + bv;
            float v1 = acc[nt][cc + 2] + bv;
            if (relu) { v0 = fmaxf(v0, 0.f); v1 = fmaxf(v1, 0.f); }
            const int pcol = n0 + nb + nt * 8 + (((r & 3) << 1) | ((r >> 2) & 1));
            if (packOut == 1) {
                ((U32*)C)[(size_t)(m0 + r0)     * N + pcol] = packA(v0);
                ((U32*)C)[(size_t)(m0 + r0 + 8) * N + pcol] = packA(v1);
            } else if (packOut == 2) {
                ((float*)C)[(size_t)(m0 + r0)     * N + pcol] = v0;
                ((float*)C)[(size_t)(m0 + r0 + 8) * N + pcol] = v1;
            } else {
                ((float*)C)[(size_t)(m0 + r0)     * N + col] = v0;
                ((float*)C)[(size_t)(m0 + r0 + 8) * N + col] = v1;
            }
        }
    }
}

// ---------------------------------------------------------------------------
// pair_mma v4 (unchanged — measured 34.0 us, occ 32.8%, 3 CTAs/SM):
// out[b,i,n,j] = sum_h relu(s2[b,i,h] + t2[b,j,h]) * fc3[n,h]
// tf32 m16n8k8; pair fragments built in registers, never materialized.
// W stores only 25 real rows; nt=3 rows 25..31 alias the s region (finite
// floats) and feed only the discarded n>=25 output columns.
// ---------------------------------------------------------------------------
#define PROW 264
#define PROW2 132
#define SM_T2F 0
#define SM_WF  (32 * PROW)
#define SM_SF  (57 * PROW)
#define PAIR_SMEM (65 * PROW * 4)   // 68640 B

__global__ __launch_bounds__(256, 3) void pair_mma(
    const float* __restrict__ s2, const float* __restrict__ t2,
    const U32* __restrict__ w3p, float* __restrict__ out)
{
    extern __shared__ float sm[];
    const int jt = blockIdx.x;   // 0..7  (j tile of 32)
    const int ig = blockIdx.y;   // 0..31 (i group of 8)
    const int b  = blockIdx.z;   // 0..3

    const int tid  = threadIdx.x;
    const int w    = tid >> 5;
    const int lane = tid & 31;
    const int g    = lane >> 2;
    const int tg   = lane & 3;
    const int wj   = w & 1;
    const int wi   = w >> 1;

    const U32 smB = (U32)__cvta_generic_to_shared(sm);

    {   // t2: 32 rows x 256 floats
        const float* t2g = t2 + (size_t)(b * 256 + jt * 32) * 256;
#pragma unroll
        for (int r = 0; r < 8; r++) {
            int q   = tid + r * 256;
            int row = q >> 6;
            int c4  = (q & 63) * 4;
            cp16(smB + (SM_T2F + row * PROW + c4) * 4, t2g + row * 256 + c4);
        }
    }
    // fc3 tf32: 25 rows x 256
    for (int q = tid; q < 1600; q += 256) {
        int row = q >> 6;
        int c4  = (q & 63) * 4;
        cp16(smB + (SM_WF + row * PROW + c4) * 4, w3p + row * 256 + c4);
    }
    {   // s2: 8 rows x 256
        const float* s2g = s2 + (size_t)(b * 256 + ig * 8) * 256;
#pragma unroll
        for (int r = 0; r < 2; r++) {
            int q   = tid + r * 256;
            int row = q >> 6;
            int c4  = (q & 63) * 4;
            cp16(smB + (SM_SF + row * PROW + c4) * 4, s2g + row * 256 + c4);
        }
    }
    cp_commit();
    cp_wait0();
    __syncthreads();

    const float2* tA2 = (const float2*)sm + (size_t)(wj * 16 + g) * PROW2 + tg;
    const float2* tW2 = (const float2*)sm + (SM_WF / 2) + (size_t)g * PROW2 + tg;
    const float2* tS2 = (const float2*)sm + (SM_SF / 2) + (size_t)(wi * 2) * PROW2 + tg;

    float acc[2][4][4];   // [i][nt][c]
#pragma unroll
    for (int i = 0; i < 2; i++)
#pragma unroll
        for (int nt = 0; nt < 4; nt++)
#pragma unroll
            for (int c = 0; c < 4; c++) acc[i][nt][c] = 0.f;

#pragma unroll 4
    for (int ks = 0; ks < 32; ks++) {
        const int o = ks * 4;
        float2 u0 = tA2[o];
        float2 u1 = tA2[o + 8 * PROW2];
        float2 wv[4];
#pragma unroll
        for (int nt = 0; nt < 4; nt++) wv[nt] = tW2[o + nt * 8 * PROW2];
#pragma unroll
        for (int i = 0; i < 2; i++) {
            float2 sv = tS2[o + i * PROW2];
            U32 a0 = tf32r(fmaxf(u0.x + sv.x, 0.f));
            U32 a1 = tf32r(fmaxf(u1.x + sv.x, 0.f));
            U32 a2 = tf32r(fmaxf(u0.y + sv.y, 0.f));
            U32 a3 = tf32r(fmaxf(u1.y + sv.y, 0.f));
#pragma unroll
            for (int nt = 0; nt < 4; nt++) {
                mma_tf32(acc[i][nt][0], acc[i][nt][1], acc[i][nt][2], acc[i][nt][3],
                         a0, a1, a2, a3,
                         __float_as_uint(wv[nt].x), __float_as_uint(wv[nt].y));
            }
        }
    }

    const int jg = jt * 32 + wj * 16 + g;
#pragma unroll
    for (int i = 0; i < 2; i++) {
        const int ii = ig * 8 + wi * 2 + i;
        float* obase = out + ((size_t)(b * 256 + ii) * 25) * 256 + jg;
#pragma unroll
        for (int nt = 0; nt < 4; nt++) {
            int n0 = nt * 8 + tg * 2;
            if (n0 < 25) {
                obase[(size_t)n0 * 256]     = acc[i][nt][0];
                obase[(size_t)n0 * 256 + 8] = acc[i][nt][2];
            }
            if (n0 + 1 < 25) {
                obase[(size_t)(n0 + 1) * 256]     = acc[i][nt][1];
                obase[(size_t)(n0 + 1) * 256 + 8] = acc[i][nt][3];
            }
        }
    }
}

// ---------------------------------------------------------------------------
// Inputs (metadata order):
// 0 input_tensor [4,256,768]  1 s_fc_w [256,768]  2 s_fc_b [256]
// 3 t_fc_w [256,768]          4 t_fc_b [256]      5 fc2_w [256,512]
// 6 fc2_b [256]               7 fc3_w [25,256]
// Output: float32 [4,256,25,256]
// ---------------------------------------------------------------------------
extern "C" void kernel_launch(void* const* d_in, const int* in_sizes, int n_in,
                              void* d_out, int out_size)
{
    const float* X  = (const float*)d_in[0];
    const float* sw = (const float*)d_in[1];
    const float* sb = (const float*)d_in[2];
    const float* tw = (const float*)d_in[3];
    const float* tb = (const float*)d_in[4];
    const float* w2 = (const float*)d_in[5];
    const float* b2 = (const float*)d_in[6];
    const float* w3 = (const float*)d_in[7];
    float* out = (float*)d_out;

    U32 *xp, *swh, *swl, *twh, *twl, *w2h, *w2l, *w3p, *gs, *gt;
    float *gs2, *gt2;
    cudaGetSymbolAddress((void**)&xp,  g_xp);
    cudaGetSymbolAddress((void**)&swh, g_swh);
    cudaGetSymbolAddress((void**)&swl, g_swl);
    cudaGetSymbolAddress((void**)&twh, g_twh);
    cudaGetSymbolAddress((void**)&twl, g_twl);
    cudaGetSymbolAddress((void**)&w2h, g_w2h);
    cudaGetSymbolAddress((void**)&w2l, g_w2l);
    cudaGetSymbolAddress((void**)&w3p, g_w3p);
    cudaGetSymbolAddress((void**)&gs,  g_s);
    cudaGetSymbolAddress((void**)&gt,  g_t);
    cudaGetSymbolAddress((void**)&gs2, g_s2);
    cudaGetSymbolAddress((void**)&gt2, g_t2);

    cudaFuncSetAttribute(gemm_bf, cudaFuncAttributeMaxDynamicSharedMemorySize,
                         GEMM_SMEM);
    cudaFuncSetAttribute(pair_mma, cudaFuncAttributeMaxDynamicSharedMemorySize,
                         PAIR_SMEM);

    prep<<<(NX + 255) / 256, 256>>>(X, sw, tw, w2, w3);

    dim3 blk(128);
    dim3 g1(256 / 32, 1024 / 32, 2);   // 512 CTAs
    gemm_bf<<<g1, blk, GEMM_SMEM>>>(xp, xp, swh, twh, swl, twl, sb, tb,
                                    gs, gt, 768, 768, 256, 1, 1);
    // s2/t2 written fp32 with h-permutation (packOut=2) for pair staging
    gemm_bf<<<g1, blk, GEMM_SMEM>>>(gs, gt, w2h, w2h + 256, w2l, w2l + 256,
                                    nullptr, b2, gs2, gt2, 256, 512, 256, 0, 2);

    dim3 g3(8, 32, 4);                 // 1024 CTAs, 256 threads
    pair_mma<<<g3, dim3(256), PAIR_SMEM>>>(gs2, gt2, w3p, out);
}

// round 13
// speedup vs baseline: 1.5386x; 1.3540x over previous
#include <cuda_runtime.h>
#include <cuda_bf16.h>

typedef unsigned int U32;

__device__ __forceinline__ U32 tf32r(float x) {
    U32 r;
    asm("cvt.rna.tf32.f32 %0, %1;" : "=r"(r) : "f"(x));
    return r;
}
__device__ __forceinline__ void mma_tf32(
    float& c0, float& c1, float& c2, float& c3,
    U32 a0, U32 a1, U32 a2, U32 a3, U32 b0, U32 b1)
{
    asm volatile(
        "mma.sync.aligned.m16n8k8.row.col.f32.tf32.tf32.f32 "
        "{%0,%1,%2,%3}, {%4,%5,%6,%7}, {%8,%9}, {%0,%1,%2,%3};"
        : "+f"(c0), "+f"(c1), "+f"(c2), "+f"(c3)
        : "r"(a0), "r"(a1), "r"(a2), "r"(a3), "r"(b0), "r"(b1));
}
__device__ __forceinline__ void mma_bf16(
    float& c0, float& c1, float& c2, float& c3,
    U32 a0, U32 a1, U32 a2, U32 a3, U32 b0, U32 b1)
{
    asm volatile(
        "mma.sync.aligned.m16n8k16.row.col.f32.bf16.bf16.f32 "
        "{%0,%1,%2,%3}, {%4,%5,%6,%7}, {%8,%9}, {%0,%1,%2,%3};"
        : "+f"(c0), "+f"(c1), "+f"(c2), "+f"(c3)
        : "r"(a0), "r"(a1), "r"(a2), "r"(a3), "r"(b0), "r"(b1));
}
__device__ __forceinline__ void cp16(U32 dst, const void* src) {
    asm volatile("cp.async.ca.shared.global [%0], [%1], 16;" :: "r"(dst), "l"(src));
}
__device__ __forceinline__ void cp_commit() { asm volatile("cp.async.commit_group;"); }
__device__ __forceinline__ void cp_wait2()  { asm volatile("cp.async.wait_group 2;"); }
__device__ __forceinline__ void cp_wait0()  { asm volatile("cp.async.wait_group 0;"); }

// bf16 hi/lo split. a = hi + lo + r, |r| <= 2^-18 |a|
__device__ __forceinline__ void bsplit(float v, unsigned short& hs, unsigned short& ls) {
    __nv_bfloat16 h = __float2bfloat16_rn(v);
    float hf = __bfloat162float(h);
    __nv_bfloat16 l = __float2bfloat16_rn(v - hf);
    hs = __bfloat16_as_ushort(h);
    ls = __bfloat16_as_ushort(l);
}
__device__ __forceinline__ U32 packA(float v) {
    unsigned short hs, ls; bsplit(v, hs, ls);
    return (U32)hs | ((U32)ls << 16);
}
// permute k within its 8-group so fragment LDS.64 gets (k, k+4) adjacent
__device__ __forceinline__ int permk(int k) {
    return (k & ~7) | ((k & 3) << 1) | ((k >> 2) & 1);
}

// Scratch (cudaMalloc forbidden; __device__ globals allowed)
__device__ U32   g_xp [1024 * 768];
__device__ U32   g_swh[256 * 768], g_swl[256 * 768];
__device__ U32   g_twh[256 * 768], g_twl[256 * 768];
__device__ U32   g_w2h[256 * 512], g_w2l[256 * 512];
__device__ U32   g_w3p[25 * 256];                 // fc3 tf32 bits, k-permuted
__device__ U32   g_s  [1024 * 256];               // stage1 out, packed-split, permuted
__device__ U32   g_t  [1024 * 256];
__device__ float g_s2 [1024 * 256];               // stage2 out, fp32, h-permuted
__device__ float g_t2 [1024 * 256];

#define NX  (1024 * 768)
#define NW  (256 * 768)
#define NW2 (256 * 512)
#define NW3 (25 * 256)

__global__ void prep(const float* __restrict__ X,
                     const float* __restrict__ sw, const float* __restrict__ tw,
                     const float* __restrict__ w2, const float* __restrict__ w3)
{
    int i = blockIdx.x * blockDim.x + threadIdx.x;
    if (i < NX) {
        int row = i / 768, k = i % 768;
        g_xp[row * 768 + permk(k)] = packA(X[i]);
    }
    if (i < NW) {
        int row = i / 768, k = i % 768;
        int o = row * 768 + permk(k);
        unsigned short hs, ls;
        bsplit(sw[i], hs, ls);
        g_swh[o] = (U32)hs | ((U32)hs << 16);
        g_swl[o] = (U32)ls;
        bsplit(tw[i], hs, ls);
        g_twh[o] = (U32)hs | ((U32)hs << 16);
        g_twl[o] = (U32)ls;
    }
    if (i < NW2) {
        int row = i / 512, k = i % 512;
        int o = row * 512 + permk(k);
        unsigned short hs, ls;
        bsplit(w2[i], hs, ls);
        g_w2h[o] = (U32)hs | ((U32)hs << 16);
        g_w2l[o] = (U32)ls;
    }
    if (i < NW3) {
        int row = i / 256, k = i % 256;
        g_w3p[row * 256 + permk(k)] = tf32r(w3[i]);
    }
}

// ---------------------------------------------------------------------------
// gemm_bf v5: 4-stage cp.async ring, 3 chunks in flight, ONE __syncthreads
// per chunk. Commit EVERY iteration (empty groups keep wait_group 2 exact
// through the tail: completed >= commits-2 = kc+1 => chunk kc ready).
// Buffer reuse safe: chunk kc+3 lands in the buffer of chunk kc-1, and every
// warp finished compute(kc-1) before this iteration's sync.
// Compute body identical to R10 (proven): packed bf16-split, pure LDS+MMA.
// CTA 32m x 32n, 128 threads, K-chunk 32 words. 512 CTAs. smem 61.4 KB.
// packOut: 0 = plain fp32, 1 = packed-split U32 (permuted), 2 = fp32 permuted.
// ---------------------------------------------------------------------------
#define SKW 40
#define ARR (32 * SKW)                     // 1280 words per array
#define GBUF (3 * ARR)                     // A + Bh + Bl per stage
#define NSTAGE 4
#define GEMM_SMEM (NSTAGE * GBUF * 4)      // 61440 bytes

__global__ __launch_bounds__(128) void gemm_bf(
    const U32* __restrict__ A0,  const U32* __restrict__ A1,
    const U32* __restrict__ Bh0, const U32* __restrict__ Bh1,
    const U32* __restrict__ Bl0, const U32* __restrict__ Bl1,
    const float* __restrict__ bias0, const float* __restrict__ bias1,
    void* C0, void* C1,
    int K, int ldb, int N, int relu, int packOut)
{
    extern __shared__ U32 smw[];

    const U32* A      = blockIdx.z ? A1 : A0;
    const U32* Bhp    = blockIdx.z ? Bh1 : Bh0;
    const U32* Blp    = blockIdx.z ? Bl1 : Bl0;
    const float* bias = blockIdx.z ? bias1 : bias0;
    void* C           = blockIdx.z ? C1 : C0;

    const int m0 = blockIdx.y * 32;
    const int n0 = blockIdx.x * 32;

    const int tid  = threadIdx.x;
    const int w    = tid >> 5;
    const int lane = tid & 31;
    const int g    = lane >> 2;
    const int tg   = lane & 3;
    const int r0   = (w & 1) * 16 + g;     // m rows r0, r0+8
    const int nb   = (w >> 1) * 16;        // n half

    const U32 smB = (U32)__cvta_generic_to_shared(smw);

    // loader: row = tid>>2 (0..31), words (tid&3)*8 .. +7 (2 cp16 per array)
    const int lrow = tid >> 2;
    const int lk   = (tid & 3) * 8;

    const U32* Aptr  = A   + (size_t)(m0 + lrow) * K   + lk;
    const U32* Bhptr = Bhp + (size_t)(n0 + lrow) * ldb + lk;
    const U32* Blptr = Blp + (size_t)(n0 + lrow) * ldb + lk;

    const int KC = K / 32;

    float acc[2][4];
#pragma unroll
    for (int nt = 0; nt < 2; nt++)
#pragma unroll
        for (int c = 0; c < 4; c++) acc[nt][c] = 0.f;

    // prologue: stage chunks 0..2 into ring slots 0..2
#pragma unroll
    for (int s = 0; s < 3; s++) {
        if (s < KC) {
            const int ko = s * 32;
            const U32 d = smB + s * GBUF * 4 + (lrow * SKW + lk) * 4;
#pragma unroll
            for (int c = 0; c < 2; c++) {
                cp16(d +            c * 16, Aptr  + ko + c * 4);
                cp16(d + ARR * 4  + c * 16, Bhptr + ko + c * 4);
                cp16(d + ARR * 8  + c * 16, Blptr + ko + c * 4);
            }
        }
        cp_commit();
    }

    for (int kc = 0; kc < KC; kc++) {
        const int cur = kc & (NSTAGE - 1);
        cp_wait2();              // first kc+1 groups done -> chunk kc ready
        __syncthreads();

        // issue chunk kc+3 into slot (kc+3)%4 (= slot of chunk kc-1, freed)
        if (kc + 3 < KC) {
            const int ko = (kc + 3) * 32;
            const U32 d = smB + ((kc + 3) & (NSTAGE - 1)) * GBUF * 4
                        + (lrow * SKW + lk) * 4;
#pragma unroll
            for (int c = 0; c < 2; c++) {
                cp16(d +            c * 16, Aptr  + ko + c * 4);
                cp16(d + ARR * 4  + c * 16, Bhptr + ko + c * 4);
                cp16(d + ARR * 8  + c * 16, Blptr + ko + c * 4);
            }
        }
        cp_commit();             // always commit (possibly empty group)

        const U32* base = smw + cur * GBUF;
#pragma unroll
        for (int ks = 0; ks < 4; ks++) {
            const int o = ks * 8 + 2 * tg;
            uint2 aA = *(const uint2*)&base[ r0      * SKW + o];
            uint2 aB = *(const uint2*)&base[(r0 + 8) * SKW + o];
#pragma unroll
            for (int nt = 0; nt < 2; nt++) {
                uint2 bh = *(const uint2*)&base[ARR     + (nb + nt * 8 + g) * SKW + o];
                uint2 bl = *(const uint2*)&base[ARR * 2 + (nb + nt * 8 + g) * SKW + o];
                mma_bf16(acc[nt][0], acc[nt][1], acc[nt][2], acc[nt][3],
                         aA.x, aB.x, aA.y, aB.y, bh.x, bh.y);
                mma_bf16(acc[nt][0], acc[nt][1], acc[nt][2], acc[nt][3],
                         aA.x, aB.x, aA.y, aB.y, bl.x, bl.y);
            }
        }
    }
    cp_wait0();

    // epilogue: c0:(r0,2tg) c1:(r0,2tg+1) c2:(r0+8,2tg) c3:(r0+8,2tg+1)
#pragma unroll
    for (int nt = 0; nt < 2; nt++) {
#pragma unroll
        for (int cc = 0; cc < 2; cc++) {
            const int r   = 2 * tg + cc;
            const int col = n0 + nb + nt * 8 + r;
            float bv = bias ? bias[col] : 0.f;
            float v0 = acc[nt][cc]     + bv;
            float v1 = acc[nt][cc + 2] + bv;
            if (relu) { v0 = fmaxf(v0, 0.f); v1 = fmaxf(v1, 0.f); }
            const int pcol = n0 + nb + nt * 8 + (((r & 3) << 1) | ((r >> 2) & 1));
            if (packOut == 1) {
                ((U32*)C)[(size_t)(m0 + r0)     * N + pcol] = packA(v0);
                ((U32*)C)[(size_t)(m0 + r0 + 8) * N + pcol] = packA(v1);
            } else if (packOut == 2) {
                ((float*)C)[(size_t)(m0 + r0)     * N + pcol] = v0;
                ((float*)C)[(size_t)(m0 + r0 + 8) * N + pcol] = v1;
            } else {
                ((float*)C)[(size_t)(m0 + r0)     * N + col] = v0;
                ((float*)C)[(size_t)(m0 + r0 + 8) * N + col] = v1;
            }
        }
    }
}

// ---------------------------------------------------------------------------
// pair_mma v4 (unchanged — measured 34.0-34.5 us across 3 runs, 3 CTAs/SM):
// out[b,i,n,j] = sum_h relu(s2[b,i,h] + t2[b,j,h]) * fc3[n,h]
// tf32 m16n8k8; pair fragments built in registers, never materialized.
// W stores only 25 real rows; nt=3 rows 25..31 alias the s region (finite
// floats) and feed only the discarded n>=25 output columns.
// ---------------------------------------------------------------------------
#define PROW 264
#define PROW2 132
#define SM_T2F 0
#define SM_WF  (32 * PROW)
#define SM_SF  (57 * PROW)
#define PAIR_SMEM (65 * PROW * 4)   // 68640 B

__global__ __launch_bounds__(256, 3) void pair_mma(
    const float* __restrict__ s2, const float* __restrict__ t2,
    const U32* __restrict__ w3p, float* __restrict__ out)
{
    extern __shared__ float sm[];
    const int jt = blockIdx.x;   // 0..7  (j tile of 32)
    const int ig = blockIdx.y;   // 0..31 (i group of 8)
    const int b  = blockIdx.z;   // 0..3

    const int tid  = threadIdx.x;
    const int w    = tid >> 5;
    const int lane = tid & 31;
    const int g    = lane >> 2;
    const int tg   = lane & 3;
    const int wj   = w & 1;
    const int wi   = w >> 1;

    const U32 smB = (U32)__cvta_generic_to_shared(sm);

    {   // t2: 32 rows x 256 floats
        const float* t2g = t2 + (size_t)(b * 256 + jt * 32) * 256;
#pragma unroll
        for (int r = 0; r < 8; r++) {
            int q   = tid + r * 256;
            int row = q >> 6;
            int c4  = (q & 63) * 4;
            cp16(smB + (SM_T2F + row * PROW + c4) * 4, t2g + row * 256 + c4);
        }
    }
    // fc3 tf32: 25 rows x 256
    for (int q = tid; q < 1600; q += 256) {
        int row = q >> 6;
        int c4  = (q & 63) * 4;
        cp16(smB + (SM_WF + row * PROW + c4) * 4, w3p + row * 256 + c4);
    }
    {   // s2: 8 rows x 256
        const float* s2g = s2 + (size_t)(b * 256 + ig * 8) * 256;
#pragma unroll
        for (int r = 0; r < 2; r++) {
            int q   = tid + r * 256;
            int row = q >> 6;
            int c4  = (q & 63) * 4;
            cp16(smB + (SM_SF + row * PROW + c4) * 4, s2g + row * 256 + c4);
        }
    }
    cp_commit();
    cp_wait0();
    __syncthreads();

    const float2* tA2 = (const float2*)sm + (size_t)(wj * 16 + g) * PROW2 + tg;
    const float2* tW2 = (const float2*)sm + (SM_WF / 2) + (size_t)g * PROW2 + tg;
    const float2* tS2 = (const float2*)sm + (SM_SF / 2) + (size_t)(wi * 2) * PROW2 + tg;

    float acc[2][4][4];   // [i][nt][c]
#pragma unroll
    for (int i = 0; i < 2; i++)
#pragma unroll
        for (int nt = 0; nt < 4; nt++)
#pragma unroll
            for (int c = 0; c < 4; c++) acc[i][nt][c] = 0.f;

#pragma unroll 4
    for (int ks = 0; ks < 32; ks++) {
        const int o = ks * 4;
        float2 u0 = tA2[o];
        float2 u1 = tA2[o + 8 * PROW2];
        float2 wv[4];
#pragma unroll
        for (int nt = 0; nt < 4; nt++) wv[nt] = tW2[o + nt * 8 * PROW2];
#pragma unroll
        for (int i = 0; i < 2; i++) {
            float2 sv = tS2[o + i * PROW2];
            U32 a0 = tf32r(fmaxf(u0.x + sv.x, 0.f));
            U32 a1 = tf32r(fmaxf(u1.x + sv.x, 0.f));
            U32 a2 = tf32r(fmaxf(u0.y + sv.y, 0.f));
            U32 a3 = tf32r(fmaxf(u1.y + sv.y, 0.f));
#pragma unroll
            for (int nt = 0; nt < 4; nt++) {
                mma_tf32(acc[i][nt][0], acc[i][nt][1], acc[i][nt][2], acc[i][nt][3],
                         a0, a1, a2, a3,
                         __float_as_uint(wv[nt].x), __float_as_uint(wv[nt].y));
            }
        }
    }

    const int jg = jt * 32 + wj * 16 + g;
#pragma unroll
    for (int i = 0; i < 2; i++) {
        const int ii = ig * 8 + wi * 2 + i;
        float* obase = out + ((size_t)(b * 256 + ii) * 25) * 256 + jg;
#pragma unroll
        for (int nt = 0; nt < 4; nt++) {
            int n0 = nt * 8 + tg * 2;
            if (n0 < 25) {
                obase[(size_t)n0 * 256]     = acc[i][nt][0];
                obase[(size_t)n0 * 256 + 8] = acc[i][nt][2];
            }
            if (n0 + 1 < 25) {
                obase[(size_t)(n0 + 1) * 256]     = acc[i][nt][1];
                obase[(size_t)(n0 + 1) * 256 + 8] = acc[i][nt][3];
            }
        }
    }
}

// ---------------------------------------------------------------------------
// Inputs (metadata order):
// 0 input_tensor [4,256,768]  1 s_fc_w [256,768]  2 s_fc_b [256]
// 3 t_fc_w [256,768]          4 t_fc_b [256]      5 fc2_w [256,512]
// 6 fc2_b [256]               7 fc3_w [25,256]
// Output: float32 [4,256,25,256]
// ---------------------------------------------------------------------------
extern "C" void kernel_launch(void* const* d_in, const int* in_sizes, int n_in,
                              void* d_out, int out_size)
{
    const float* X  = (const float*)d_in[0];
    const float* sw = (const float*)d_in[1];
    const float* sb = (const float*)d_in[2];
    const float* tw = (const float*)d_in[3];
    const float* tb = (const float*)d_in[4];
    const float* w2 = (const float*)d_in[5];
    const float* b2 = (const float*)d_in[6];
    const float* w3 = (const float*)d_in[7];
    float* out = (float*)d_out;

    U32 *xp, *swh, *swl, *twh, *twl, *w2h, *w2l, *w3p, *gs, *gt;
    float *gs2, *gt2;
    cudaGetSymbolAddress((void**)&xp,  g_xp);
    cudaGetSymbolAddress((void**)&swh, g_swh);
    cudaGetSymbolAddress((void**)&swl, g_swl);
    cudaGetSymbolAddress((void**)&twh, g_twh);
    cudaGetSymbolAddress((void**)&twl, g_twl);
    cudaGetSymbolAddress((void**)&w2h, g_w2h);
    cudaGetSymbolAddress((void**)&w2l, g_w2l);
    cudaGetSymbolAddress((void**)&w3p, g_w3p);
    cudaGetSymbolAddress((void**)&gs,  g_s);
    cudaGetSymbolAddress((void**)&gt,  g_t);
    cudaGetSymbolAddress((void**)&gs2, g_s2);
    cudaGetSymbolAddress((void**)&gt2, g_t2);

    cudaFuncSetAttribute(gemm_bf, cudaFuncAttributeMaxDynamicSharedMemorySize,
                         GEMM_SMEM);
    cudaFuncSetAttribute(pair_mma, cudaFuncAttributeMaxDynamicSharedMemorySize,
                         PAIR_SMEM);

    prep<<<(NX + 255) / 256, 256>>>(X, sw, tw, w2, w3);

    dim3 blk(128);
    dim3 g1(256 / 32, 1024 / 32, 2);   // 512 CTAs
    gemm_bf<<<g1, blk, GEMM_SMEM>>>(xp, xp, swh, twh, swl, twl, sb, tb,
                                    gs, gt, 768, 768, 256, 1, 1);
    // s2/t2 written fp32 with h-permutation (packOut=2) for pair staging
    gemm_bf<<<g1, blk, GEMM_SMEM>>>(gs, gt, w2h, w2h + 256, w2l, w2l + 256,
                                    nullptr, b2, gs2, gt2, 256, 512, 256, 0, 2);

    dim3 g3(8, 32, 4);                 // 1024 CTAs, 256 threads
    pair_mma<<<g3, dim3(256), PAIR_SMEM>>>(gs2, gt2, w3p, out);
}